// round 12
// baseline (speedup 1.0000x reference)
#include <cuda_runtime.h>
#include <cuda_fp16.h>
#include <cstdint>

// GRU fused kernel v7: B=16, T=60, S=2000, C=64, H=64.
// Base = v3 (best, 413us): warp-private recurrence, one warp = 16 sequences x
// all 192 gate cols, h in f32 registers, single-fp16 weights, no barriers.
// v7 adds, in order of expected impact:
//  1) warp DE-PHASING: warps 4-7 (second warp on each SMSP) run 2 redundant
//     x-GEMM rounds pre-loop -> ~half-step phase offset so one warp's MUFU
//     (elementwise) phase overlaps the other's tensor phase instead of
//     convoying (the 2.4x gap between 413us and the ~175us overlap floor).
//  2) software-pipelined step: x LDGs for t+1 issued before elementwise(t),
//     x-GEMM(t+1) after it.
//  3) paired-reciprocal activations (v5-validated): 9 MUFU / 2 elements.

namespace {

constexpr int kT = 60, kS = 2000, kC = 64, kH = 64, kG = 192;
constexpr int PITCH = 72;      // fp16 elems per weight row (144B) -> conflict-free ldsm
constexpr int THREADS = 256;   // 8 warps, 128 rows per CTA
constexpr int NROWS = 16 * 2000;

constexpr int OFF_WIH = 0;
constexpr int OFF_WHH = OFF_WIH + kG * PITCH * 2;
constexpr int OFF_BRZ = OFF_WHH + kG * PITCH * 2;   // f32[128]
constexpr int OFF_BIN = OFF_BRZ + 128 * 4;          // f32[64]
constexpr int OFF_BHN = OFF_BIN + 64 * 4;           // f32[64]
constexpr int SMEM_BYTES = OFF_BHN + 64 * 4;        // ~56.3 KB

__device__ __forceinline__ uint32_t smem_u32(const void* p) {
  return (uint32_t)__cvta_generic_to_shared(p);
}

__device__ __forceinline__ void ldsm4(uint32_t r[4], uint32_t addr) {
  asm volatile("ldmatrix.sync.aligned.m8n8.x4.shared.b16 {%0,%1,%2,%3}, [%4];\n"
               : "=r"(r[0]), "=r"(r[1]), "=r"(r[2]), "=r"(r[3]) : "r"(addr));
}

__device__ __forceinline__ void mma16816(float d[4], const uint32_t a[4],
                                         const uint32_t b0, const uint32_t b1) {
  asm volatile(
      "mma.sync.aligned.m16n8k16.row.col.f32.f16.f16.f32 "
      "{%0,%1,%2,%3},{%4,%5,%6,%7},{%8,%9},{%0,%1,%2,%3};\n"
      : "+f"(d[0]), "+f"(d[1]), "+f"(d[2]), "+f"(d[3])
      : "r"(a[0]), "r"(a[1]), "r"(a[2]), "r"(a[3]), "r"(b0), "r"(b1));
}

__device__ __forceinline__ uint32_t pack_f16x2(float a, float b) {
  __half2 h = __floats2half2_rn(a, b);
  return *reinterpret_cast<uint32_t*>(&h);
}

__device__ __forceinline__ float frcp_fast(float x) {
  float r;
  asm("rcp.approx.f32 %0, %1;" : "=f"(r) : "f"(x));
  return r;
}

}  // namespace

__global__ void __launch_bounds__(THREADS, 1)
gru_fused_kernel(const float* __restrict__ chars,
                 const float* __restrict__ Wih,
                 const float* __restrict__ Whh,
                 const float* __restrict__ bih,
                 const float* __restrict__ bhh,
                 float* __restrict__ out) {
  extern __shared__ char smem[];
  __half* wih_s = reinterpret_cast<__half*>(smem + OFF_WIH);
  __half* whh_s = reinterpret_cast<__half*>(smem + OFF_WHH);
  float* brz = reinterpret_cast<float*>(smem + OFF_BRZ);
  float* bin_s = reinterpret_cast<float*>(smem + OFF_BIN);
  float* bhn_s = reinterpret_cast<float*>(smem + OFF_BHN);

  const int tid = threadIdx.x;
  const int lane = tid & 31;
  const int wid = tid >> 5;

  // ---- one-time init: fp16 weights (padded pitch), biases ----
  for (int i = tid; i < kG * kC; i += THREADS) {
    const int g = i >> 6, c = i & 63;
    wih_s[g * PITCH + c] = __float2half_rn(Wih[i]);
    whh_s[g * PITCH + c] = __float2half_rn(Whh[i]);
  }
  if (tid < 128) brz[tid] = bih[tid] + bhh[tid];
  if (tid < 64) {
    bin_s[tid] = bih[128 + tid];
    bhn_s[tid] = bhh[128 + tid];
  }
  __syncthreads();  // the only block-wide barrier

  // ---- per-warp geometry ----
  const int warp_row0 = (blockIdx.x * 8 + wid) * 16;  // 16 rows per warp
  const int bb = warp_row0 / kS;
  const int ss = warp_row0 - bb * kS;
  const int lr = lane >> 2;          // 0..7
  const int c0 = (lane & 3) * 2;     // 0,2,4,6

  const float* pxa = chars + ((size_t)bb * kT * kS + (ss + lr)) * (size_t)kC;
  const float* pxb = pxa + 8 * kC;
  const size_t tstride = (size_t)kS * kC;

  // ldsm4 lane offset for B fragments
  const int sel = lane >> 3;
  const int b_lane_off = ((lane & 7) + 8 * (sel >> 1)) * (PITCH * 2) + (sel & 1) * 16;
  const uint32_t wih_b = smem_u32(wih_s) + b_lane_off;
  const uint32_t whh_b = smem_u32(whh_s) + b_lane_off;

  // h state in f32 C-fragment layout; tile j covers cols 8j..8j+7
  float hf[8][4];
#pragma unroll
  for (int j = 0; j < 8; ++j)
#pragma unroll
    for (int e = 0; e < 4; ++e) hf[j][e] = 0.0f;

  // accumulators: tiles 0-7 r, 8-15 z, 16-23 n(x-path); accHN = h-n-path
  float acc[24][4];
  float accHN[8][4];
  uint32_t xa[4][4];

  auto init_acc = [&]() {
#pragma unroll
    for (int j = 0; j < 24; ++j)
#pragma unroll
      for (int e = 0; e < 4; ++e) acc[j][e] = 0.0f;
#pragma unroll
    for (int j = 0; j < 8; ++j)
#pragma unroll
      for (int e = 0; e < 4; ++e) accHN[j][e] = 0.0f;
  };

  auto load_pack_x = [&]() {
#pragma unroll
    for (int kk = 0; kk < 4; ++kk) {
      const float2 v0 = *reinterpret_cast<const float2*>(pxa + 16 * kk + c0);
      const float2 v1 = *reinterpret_cast<const float2*>(pxb + 16 * kk + c0);
      const float2 v2 = *reinterpret_cast<const float2*>(pxa + 16 * kk + 8 + c0);
      const float2 v3 = *reinterpret_cast<const float2*>(pxb + 16 * kk + 8 + c0);
      xa[kk][0] = pack_f16x2(v0.x, v0.y);
      xa[kk][1] = pack_f16x2(v1.x, v1.y);
      xa[kk][2] = pack_f16x2(v2.x, v2.y);
      xa[kk][3] = pack_f16x2(v3.x, v3.y);
    }
    pxa += tstride;
    pxb += tstride;
  };

  auto xgemm = [&]() {
#pragma unroll
    for (int kk = 0; kk < 4; ++kk) {
      const int koff = kk * 32;
#pragma unroll
      for (int jp = 0; jp < 12; ++jp) {
        uint32_t b[4];
        ldsm4(b, wih_b + koff + jp * (16 * PITCH * 2));
        mma16816(acc[2 * jp], xa[kk], b[0], b[1]);
        mma16816(acc[2 * jp + 1], xa[kk], b[2], b[3]);
      }
    }
  };

  // ---- prologue: x-GEMM for t=0; warps 4-7 run it 3x (2 redundant rounds)
  // to acquire a ~half-step phase offset vs the co-resident SMSP warp.
  load_pack_x();
  const int reps = (wid >= 4) ? 3 : 1;
  for (int rr = 0; rr < reps; ++rr) {
    init_acc();
    xgemm();
  }

  for (int t = 0; t < kT; ++t) {
    // ---- pack h A-fragments (C-frag layout == A-frag layout) ----
    uint32_t ha[4][4];
#pragma unroll
    for (int kk = 0; kk < 4; ++kk) {
      ha[kk][0] = pack_f16x2(hf[2 * kk][0], hf[2 * kk][1]);
      ha[kk][1] = pack_f16x2(hf[2 * kk][2], hf[2 * kk][3]);
      ha[kk][2] = pack_f16x2(hf[2 * kk + 1][0], hf[2 * kk + 1][1]);
      ha[kk][3] = pack_f16x2(hf[2 * kk + 1][2], hf[2 * kk + 1][3]);
    }

    // ---- h-path GEMM: gh = h @ Whh^T ----
#pragma unroll
    for (int kk = 0; kk < 4; ++kk) {
      const int koff = kk * 32;
#pragma unroll
      for (int jp = 0; jp < 12; ++jp) {
        uint32_t b[4];
        ldsm4(b, whh_b + koff + jp * (16 * PITCH * 2));
        float* d0 = (jp < 8) ? acc[2 * jp] : accHN[2 * (jp - 8)];
        float* d1 = (jp < 8) ? acc[2 * jp + 1] : accHN[2 * (jp - 8) + 1];
        mma16816(d0, ha[kk], b[0], b[1]);
        mma16816(d1, ha[kk], b[2], b[3]);
      }
    }

    // ---- issue next step's x loads (latency hidden under elementwise) ----
    float2 xv[16];
    const bool more = (t + 1 < kT);
    if (more) {
#pragma unroll
      for (int kk = 0; kk < 4; ++kk) {
        xv[4 * kk + 0] = *reinterpret_cast<const float2*>(pxa + 16 * kk + c0);
        xv[4 * kk + 1] = *reinterpret_cast<const float2*>(pxb + 16 * kk + c0);
        xv[4 * kk + 2] = *reinterpret_cast<const float2*>(pxa + 16 * kk + 8 + c0);
        xv[4 * kk + 3] = *reinterpret_cast<const float2*>(pxb + 16 * kk + 8 + c0);
      }
      pxa += tstride;
      pxb += tstride;
    }

    // ---- elementwise GRU update (paired reciprocals: 9 MUFU / 2 elems) ----
#pragma unroll
    for (int j = 0; j < 8; ++j) {
      const float2 bR = *reinterpret_cast<const float2*>(brz + 8 * j + c0);
      const float2 bZ = *reinterpret_cast<const float2*>(brz + 64 + 8 * j + c0);
      const float2 bN = *reinterpret_cast<const float2*>(bin_s + 8 * j + c0);
      const float2 bHN = *reinterpret_cast<const float2*>(bhn_s + 8 * j + c0);
#pragma unroll
      for (int half = 0; half < 2; ++half) {
        const int e0 = half * 2, e1 = e0 + 1;
        const float a0 = 1.0f + __expf(-(acc[j][e0] + bR.x));
        const float b0 = 1.0f + __expf(-(acc[8 + j][e0] + bZ.x));
        const float a1 = 1.0f + __expf(-(acc[j][e1] + bR.y));
        const float b1 = 1.0f + __expf(-(acc[8 + j][e1] + bZ.y));
        const float ip0 = frcp_fast(a0 * b0);
        const float ip1 = frcp_fast(a1 * b1);
        const float r0 = b0 * ip0, z0 = a0 * ip0;
        const float r1 = b1 * ip1, z1 = a1 * ip1;
        const float t0 = acc[16 + j][e0] + bN.x + r0 * (accHN[j][e0] + bHN.x);
        const float t1 = acc[16 + j][e1] + bN.y + r1 * (accHN[j][e1] + bHN.y);
        const float d0 = 1.0f + __expf(-2.0f * t0);
        const float d1 = 1.0f + __expf(-2.0f * t1);
        const float ipn = frcp_fast(d0 * d1);
        const float n0 = 2.0f * d1 * ipn - 1.0f;
        const float n1 = 2.0f * d0 * ipn - 1.0f;
        hf[j][e0] = n0 + z0 * (hf[j][e0] - n0);
        hf[j][e1] = n1 + z1 * (hf[j][e1] - n1);
      }
    }

    // ---- pipeline: pack x(t+1), re-init accs, x-GEMM(t+1) ----
    if (more) {
#pragma unroll
      for (int kk = 0; kk < 4; ++kk) {
        xa[kk][0] = pack_f16x2(xv[4 * kk + 0].x, xv[4 * kk + 0].y);
        xa[kk][1] = pack_f16x2(xv[4 * kk + 1].x, xv[4 * kk + 1].y);
        xa[kk][2] = pack_f16x2(xv[4 * kk + 2].x, xv[4 * kk + 2].y);
        xa[kk][3] = pack_f16x2(xv[4 * kk + 3].x, xv[4 * kk + 3].y);
      }
      init_acc();
      xgemm();
    }
  }

  // ---- write final h (f32 state, exact) ----
  {
    float* poa = out + (size_t)(warp_row0 + lr) * kH;
    float* pob = out + (size_t)(warp_row0 + lr + 8) * kH;
#pragma unroll
    for (int j = 0; j < 8; ++j) {
      float2 va, vb;
      va.x = hf[j][0]; va.y = hf[j][1];
      vb.x = hf[j][2]; vb.y = hf[j][3];
      *reinterpret_cast<float2*>(poa + 8 * j + c0) = va;
      *reinterpret_cast<float2*>(pob + 8 * j + c0) = vb;
    }
  }
}

extern "C" void kernel_launch(void* const* d_in, const int* in_sizes, int n_in,
                              void* d_out, int out_size) {
  const float* chars = (const float*)d_in[0];
  const float* Wih = (const float*)d_in[1];
  const float* Whh = (const float*)d_in[2];
  const float* bih = (const float*)d_in[3];
  const float* bhh = (const float*)d_in[4];
  float* out = (float*)d_out;

  cudaFuncSetAttribute(gru_fused_kernel,
                       cudaFuncAttributeMaxDynamicSharedMemorySize, SMEM_BYTES);

  const int grid = NROWS / (16 * 8);  // 250 CTAs, 8 warps each, 16 rows/warp
  gru_fused_kernel<<<grid, THREADS, SMEM_BYTES>>>(chars, Wih, Whh, bih, bhh, out);
}

// round 13
// speedup vs baseline: 1.0712x; 1.0712x over previous
#include <cuda_runtime.h>
#include <cuda_fp16.h>
#include <cstdint>

// GRU fused kernel v8: B=16, T=60, S=2000, C=64, H=64.
// Verbatim v3 base (best, 413us): warp-private recurrence, one warp = 16
// sequences x all 192 gate cols, h in f32 registers, single-fp16 weights,
// depth-1 B prefetch, no barriers in the time loop. Exactly two changes:
//  1) paired-reciprocal elementwise (v5-validated numerics): 4.5 MUFU/elem
//     instead of 6 -> EW phase 3072 -> 2304 cyc/SMSP/step.
//  2) one-time ~3000-cycle skew delay for warps 4-7 (the second warp on each
//     SMSP) via a register-neutral asm dependent-FMUL chain, so co-SMSP warps
//     run half a step out of phase: one warp's MUFU (EW) phase overlaps the
//     other's tensor/ldsm (GEMM) phase instead of convoying.

namespace {

constexpr int kT = 60, kS = 2000, kC = 64, kH = 64, kG = 192;
constexpr int PITCH = 72;      // fp16 elems per weight row (144B) -> conflict-free ldsm
constexpr int THREADS = 256;   // 8 warps, 128 rows per CTA
constexpr int NROWS = 16 * 2000;

constexpr int OFF_WIH = 0;
constexpr int OFF_WHH = OFF_WIH + kG * PITCH * 2;
constexpr int OFF_BRZ = OFF_WHH + kG * PITCH * 2;   // f32[128]
constexpr int OFF_BIN = OFF_BRZ + 128 * 4;          // f32[64]
constexpr int OFF_BHN = OFF_BIN + 64 * 4;           // f32[64]
constexpr int SMEM_BYTES = OFF_BHN + 64 * 4;        // ~56.3 KB

__device__ __forceinline__ uint32_t smem_u32(const void* p) {
  return (uint32_t)__cvta_generic_to_shared(p);
}

__device__ __forceinline__ void ldsm4(uint32_t r[4], uint32_t addr) {
  asm volatile("ldmatrix.sync.aligned.m8n8.x4.shared.b16 {%0,%1,%2,%3}, [%4];\n"
               : "=r"(r[0]), "=r"(r[1]), "=r"(r[2]), "=r"(r[3]) : "r"(addr));
}

__device__ __forceinline__ void mma16816(float d[4], const uint32_t a[4],
                                         const uint32_t b0, const uint32_t b1) {
  asm volatile(
      "mma.sync.aligned.m16n8k16.row.col.f32.f16.f16.f32 "
      "{%0,%1,%2,%3},{%4,%5,%6,%7},{%8,%9},{%0,%1,%2,%3};\n"
      : "+f"(d[0]), "+f"(d[1]), "+f"(d[2]), "+f"(d[3])
      : "r"(a[0]), "r"(a[1]), "r"(a[2]), "r"(a[3]), "r"(b0), "r"(b1));
}

__device__ __forceinline__ uint32_t pack_f16x2(float a, float b) {
  __half2 h = __floats2half2_rn(a, b);
  return *reinterpret_cast<uint32_t*>(&h);
}

__device__ __forceinline__ float frcp_fast(float x) {
  float r;
  asm("rcp.approx.f32 %0, %1;" : "=f"(r) : "f"(x));
  return r;
}

}  // namespace

__global__ void __launch_bounds__(THREADS, 1)
gru_fused_kernel(const float* __restrict__ chars,
                 const float* __restrict__ Wih,
                 const float* __restrict__ Whh,
                 const float* __restrict__ bih,
                 const float* __restrict__ bhh,
                 float* __restrict__ out) {
  extern __shared__ char smem[];
  __half* wih_s = reinterpret_cast<__half*>(smem + OFF_WIH);
  __half* whh_s = reinterpret_cast<__half*>(smem + OFF_WHH);
  float* brz = reinterpret_cast<float*>(smem + OFF_BRZ);
  float* bin_s = reinterpret_cast<float*>(smem + OFF_BIN);
  float* bhn_s = reinterpret_cast<float*>(smem + OFF_BHN);

  const int tid = threadIdx.x;
  const int lane = tid & 31;
  const int wid = tid >> 5;

  // ---- one-time init: fp16 weights (padded pitch), biases ----
  for (int i = tid; i < kG * kC; i += THREADS) {
    const int g = i >> 6, c = i & 63;
    wih_s[g * PITCH + c] = __float2half_rn(Wih[i]);
    whh_s[g * PITCH + c] = __float2half_rn(Whh[i]);
  }
  if (tid < 128) brz[tid] = bih[tid] + bhh[tid];
  if (tid < 64) {
    bin_s[tid] = bih[128 + tid];
    bhn_s[tid] = bhh[128 + tid];
  }
  __syncthreads();  // the only block-wide barrier

  // ---- register-neutral phase skew: second warp of each SMSP (wid>=4)
  // burns ~3000 cycles once so co-SMSP warps run ~half a step out of phase.
  if (wid >= 4) {
    float v = 1.0f + (float)lane;
#pragma unroll 1
    for (int i = 0; i < 750; ++i) {
      asm volatile("mul.rn.f32 %0, %0, %1;" : "+f"(v) : "f"(0.99999994f));
    }
    // v stays in [0,33]; asm volatile prevents elimination, branch never taken
    if (v > 1e30f) brz[64] = v;
  }

  // ---- per-warp geometry ----
  const int warp_row0 = (blockIdx.x * 8 + wid) * 16;  // 16 rows per warp
  const int bb = warp_row0 / kS;
  const int ss = warp_row0 - bb * kS;
  const int lr = lane >> 2;          // 0..7
  const int c0 = (lane & 3) * 2;     // 0,2,4,6

  const float* pxa = chars + ((size_t)bb * kT * kS + (ss + lr)) * (size_t)kC;
  const float* pxb = pxa + 8 * kC;
  const size_t tstride = (size_t)kS * kC;

  // ldsm4 lane offset for B fragments
  const int sel = lane >> 3;
  const int b_lane_off = ((lane & 7) + 8 * (sel >> 1)) * (PITCH * 2) + (sel & 1) * 16;
  const uint32_t wih_b = smem_u32(wih_s) + b_lane_off;
  const uint32_t whh_b = smem_u32(whh_s) + b_lane_off;

  // h state in f32 C-fragment layout; tile j covers cols 8j..8j+7
  float hf[8][4];
#pragma unroll
  for (int j = 0; j < 8; ++j)
#pragma unroll
    for (int e = 0; e < 4; ++e) hf[j][e] = 0.0f;

  for (int t = 0; t < kT; ++t) {
    // ---- load x_t and pack to fp16 A-fragments immediately ----
    uint32_t xa[4][4];  // [kk][frag]
#pragma unroll
    for (int kk = 0; kk < 4; ++kk) {
      const float2 v0 = *reinterpret_cast<const float2*>(pxa + 16 * kk + c0);
      const float2 v1 = *reinterpret_cast<const float2*>(pxb + 16 * kk + c0);
      const float2 v2 = *reinterpret_cast<const float2*>(pxa + 16 * kk + 8 + c0);
      const float2 v3 = *reinterpret_cast<const float2*>(pxb + 16 * kk + 8 + c0);
      xa[kk][0] = pack_f16x2(v0.x, v0.y);
      xa[kk][1] = pack_f16x2(v1.x, v1.y);
      xa[kk][2] = pack_f16x2(v2.x, v2.y);
      xa[kk][3] = pack_f16x2(v3.x, v3.y);
    }
    pxa += tstride;
    pxb += tstride;

    // pack h A-fragments (C-frag layout matches A-frag layout)
    uint32_t ha[4][4];
#pragma unroll
    for (int kk = 0; kk < 4; ++kk) {
      ha[kk][0] = pack_f16x2(hf[2 * kk][0], hf[2 * kk][1]);
      ha[kk][1] = pack_f16x2(hf[2 * kk][2], hf[2 * kk][3]);
      ha[kk][2] = pack_f16x2(hf[2 * kk + 1][0], hf[2 * kk + 1][1]);
      ha[kk][3] = pack_f16x2(hf[2 * kk + 1][2], hf[2 * kk + 1][3]);
    }

    // accumulators: tiles 0-7 r, 8-15 z, 16-23 n(x-path); accHN = h-n-path
    float acc[24][4];
    float accHN[8][4];
#pragma unroll
    for (int j = 0; j < 24; ++j)
#pragma unroll
      for (int e = 0; e < 4; ++e) acc[j][e] = 0.0f;
#pragma unroll
    for (int j = 0; j < 8; ++j)
#pragma unroll
      for (int e = 0; e < 4; ++e) accHN[j][e] = 0.0f;

    // ---- h-path GEMM: gh = h @ Whh^T (depth-1 rotating prefetch) ----
    {
      uint32_t bcur[4], bnext[4];
      ldsm4(bcur, whh_b);  // kk=0, jp=0
#pragma unroll
      for (int kk = 0; kk < 4; ++kk) {
#pragma unroll
        for (int jp = 0; jp < 12; ++jp) {
          const int nkk = (jp == 11) ? kk + 1 : kk;
          const int njp = (jp == 11) ? 0 : jp + 1;
          if (!(kk == 3 && jp == 11)) {
            ldsm4(bnext, whh_b + nkk * 32 + njp * (16 * PITCH * 2));
          }
          float* d0 = (jp < 8) ? acc[2 * jp] : accHN[2 * (jp - 8)];
          float* d1 = (jp < 8) ? acc[2 * jp + 1] : accHN[2 * (jp - 8) + 1];
          mma16816(d0, ha[kk], bcur[0], bcur[1]);
          mma16816(d1, ha[kk], bcur[2], bcur[3]);
          bcur[0] = bnext[0]; bcur[1] = bnext[1];
          bcur[2] = bnext[2]; bcur[3] = bnext[3];
        }
      }
    }

    // ---- x-path GEMM: gi = x @ Wih^T (depth-1 rotating prefetch) ----
    {
      uint32_t bcur[4], bnext[4];
      ldsm4(bcur, wih_b);
#pragma unroll
      for (int kk = 0; kk < 4; ++kk) {
#pragma unroll
        for (int jp = 0; jp < 12; ++jp) {
          const int nkk = (jp == 11) ? kk + 1 : kk;
          const int njp = (jp == 11) ? 0 : jp + 1;
          if (!(kk == 3 && jp == 11)) {
            ldsm4(bnext, wih_b + nkk * 32 + njp * (16 * PITCH * 2));
          }
          mma16816(acc[2 * jp], xa[kk], bcur[0], bcur[1]);
          mma16816(acc[2 * jp + 1], xa[kk], bcur[2], bcur[3]);
          bcur[0] = bnext[0]; bcur[1] = bnext[1];
          bcur[2] = bnext[2]; bcur[3] = bnext[3];
        }
      }
    }

    // ---- elementwise GRU update (paired reciprocals: 4.5 MUFU / elem) ----
#pragma unroll
    for (int j = 0; j < 8; ++j) {
      const float2 bR = *reinterpret_cast<const float2*>(brz + 8 * j + c0);
      const float2 bZ = *reinterpret_cast<const float2*>(brz + 64 + 8 * j + c0);
      const float2 bN = *reinterpret_cast<const float2*>(bin_s + 8 * j + c0);
      const float2 bHN = *reinterpret_cast<const float2*>(bhn_s + 8 * j + c0);
#pragma unroll
      for (int half = 0; half < 2; ++half) {
        const int e0 = half * 2, e1 = e0 + 1;
        const float a0 = 1.0f + __expf(-(acc[j][e0] + bR.x));
        const float b0 = 1.0f + __expf(-(acc[8 + j][e0] + bZ.x));
        const float a1 = 1.0f + __expf(-(acc[j][e1] + bR.y));
        const float b1 = 1.0f + __expf(-(acc[8 + j][e1] + bZ.y));
        const float ip0 = frcp_fast(a0 * b0);
        const float ip1 = frcp_fast(a1 * b1);
        const float r0 = b0 * ip0, z0 = a0 * ip0;
        const float r1 = b1 * ip1, z1 = a1 * ip1;
        const float t0 = acc[16 + j][e0] + bN.x + r0 * (accHN[j][e0] + bHN.x);
        const float t1 = acc[16 + j][e1] + bN.y + r1 * (accHN[j][e1] + bHN.y);
        const float d0 = 1.0f + __expf(-2.0f * t0);
        const float d1 = 1.0f + __expf(-2.0f * t1);
        const float ipn = frcp_fast(d0 * d1);
        const float n0 = 2.0f * d1 * ipn - 1.0f;
        const float n1 = 2.0f * d0 * ipn - 1.0f;
        hf[j][e0] = n0 + z0 * (hf[j][e0] - n0);
        hf[j][e1] = n1 + z1 * (hf[j][e1] - n1);
      }
    }
  }

  // ---- write final h (f32 state, exact) ----
  {
    float* poa = out + (size_t)(warp_row0 + lr) * kH;
    float* pob = out + (size_t)(warp_row0 + lr + 8) * kH;
#pragma unroll
    for (int j = 0; j < 8; ++j) {
      float2 va, vb;
      va.x = hf[j][0]; va.y = hf[j][1];
      vb.x = hf[j][2]; vb.y = hf[j][3];
      *reinterpret_cast<float2*>(poa + 8 * j + c0) = va;
      *reinterpret_cast<float2*>(pob + 8 * j + c0) = vb;
    }
  }
}

extern "C" void kernel_launch(void* const* d_in, const int* in_sizes, int n_in,
                              void* d_out, int out_size) {
  const float* chars = (const float*)d_in[0];
  const float* Wih = (const float*)d_in[1];
  const float* Whh = (const float*)d_in[2];
  const float* bih = (const float*)d_in[3];
  const float* bhh = (const float*)d_in[4];
  float* out = (float*)d_out;

  cudaFuncSetAttribute(gru_fused_kernel,
                       cudaFuncAttributeMaxDynamicSharedMemorySize, SMEM_BYTES);

  const int grid = NROWS / (16 * 8);  // 250 CTAs, 8 warps each, 16 rows/warp
  gru_fused_kernel<<<grid, THREADS, SMEM_BYTES>>>(chars, Wih, Whh, bih, bhh, out);
}

// round 15
// speedup vs baseline: 1.3961x; 1.3033x over previous
#include <cuda_runtime.h>
#include <cuda_fp16.h>
#include <cstdint>

// GRU fused kernel v9: B=16, T=60, S=2000, C=64, H=64.
// Verbatim v3 base (best, 413us): warp-private recurrence, one warp = 16
// sequences x all 192 gate cols, h in f32 registers, single-fp16 weights,
// depth-1 B prefetch, no barriers in the time loop.
// SINGLE change vs v3: the elementwise GRU update uses MUFU.TANH
// (tanh.approx.f32) for all three activations:
//   sigmoid(x) = 0.5*tanh(0.5*x) + 0.5   (0.5 folded into stored r/z bias)
//   n = tanh(t) directly
// -> ~11 instr + 3 MUFU per element instead of ~19 instr + 6 MUFU, deleting
// ~250 instructions/thread/step from the EW phase that co-dominates the step.

namespace {

constexpr int kT = 60, kS = 2000, kC = 64, kH = 64, kG = 192;
constexpr int PITCH = 72;      // fp16 elems per weight row (144B) -> conflict-free ldsm
constexpr int THREADS = 256;   // 8 warps, 128 rows per CTA
constexpr int NROWS = 16 * 2000;

constexpr int OFF_WIH = 0;
constexpr int OFF_WHH = OFF_WIH + kG * PITCH * 2;
constexpr int OFF_BRZ = OFF_WHH + kG * PITCH * 2;   // f32[128], pre-scaled by 0.5
constexpr int OFF_BIN = OFF_BRZ + 128 * 4;          // f32[64]
constexpr int OFF_BHN = OFF_BIN + 64 * 4;           // f32[64]
constexpr int SMEM_BYTES = OFF_BHN + 64 * 4;        // ~56.3 KB

__device__ __forceinline__ uint32_t smem_u32(const void* p) {
  return (uint32_t)__cvta_generic_to_shared(p);
}

__device__ __forceinline__ void ldsm4(uint32_t r[4], uint32_t addr) {
  asm volatile("ldmatrix.sync.aligned.m8n8.x4.shared.b16 {%0,%1,%2,%3}, [%4];\n"
               : "=r"(r[0]), "=r"(r[1]), "=r"(r[2]), "=r"(r[3]) : "r"(addr));
}

__device__ __forceinline__ void mma16816(float d[4], const uint32_t a[4],
                                         const uint32_t b0, const uint32_t b1) {
  asm volatile(
      "mma.sync.aligned.m16n8k16.row.col.f32.f16.f16.f32 "
      "{%0,%1,%2,%3},{%4,%5,%6,%7},{%8,%9},{%0,%1,%2,%3};\n"
      : "+f"(d[0]), "+f"(d[1]), "+f"(d[2]), "+f"(d[3])
      : "r"(a[0]), "r"(a[1]), "r"(a[2]), "r"(a[3]), "r"(b0), "r"(b1));
}

__device__ __forceinline__ uint32_t pack_f16x2(float a, float b) {
  __half2 h = __floats2half2_rn(a, b);
  return *reinterpret_cast<uint32_t*>(&h);
}

__device__ __forceinline__ float ftanh(float x) {
  float r;
  asm("tanh.approx.f32 %0, %1;" : "=f"(r) : "f"(x));
  return r;
}

// sigmoid(2y) = 0.5*tanh(y) + 0.5 ; caller passes y = 0.5*x (bias pre-scaled)
__device__ __forceinline__ float fsigmoid_half(float y) {
  return fmaf(0.5f, ftanh(y), 0.5f);
}

}  // namespace

__global__ void __launch_bounds__(THREADS, 1)
gru_fused_kernel(const float* __restrict__ chars,
                 const float* __restrict__ Wih,
                 const float* __restrict__ Whh,
                 const float* __restrict__ bih,
                 const float* __restrict__ bhh,
                 float* __restrict__ out) {
  extern __shared__ char smem[];
  __half* wih_s = reinterpret_cast<__half*>(smem + OFF_WIH);
  __half* whh_s = reinterpret_cast<__half*>(smem + OFF_WHH);
  float* brz = reinterpret_cast<float*>(smem + OFF_BRZ);
  float* bin_s = reinterpret_cast<float*>(smem + OFF_BIN);
  float* bhn_s = reinterpret_cast<float*>(smem + OFF_BHN);

  const int tid = threadIdx.x;
  const int lane = tid & 31;
  const int wid = tid >> 5;

  // ---- one-time init: fp16 weights (padded pitch), biases ----
  for (int i = tid; i < kG * kC; i += THREADS) {
    const int g = i >> 6, c = i & 63;
    wih_s[g * PITCH + c] = __float2half_rn(Wih[i]);
    whh_s[g * PITCH + c] = __float2half_rn(Whh[i]);
  }
  // r/z bias pre-scaled by 0.5 for the sigmoid-via-tanh identity
  if (tid < 128) brz[tid] = 0.5f * (bih[tid] + bhh[tid]);
  if (tid < 64) {
    bin_s[tid] = bih[128 + tid];
    bhn_s[tid] = bhh[128 + tid];
  }
  __syncthreads();  // the only block-wide barrier

  // ---- per-warp geometry ----
  const int warp_row0 = (blockIdx.x * 8 + wid) * 16;  // 16 rows per warp
  const int bb = warp_row0 / kS;
  const int ss = warp_row0 - bb * kS;
  const int lr = lane >> 2;          // 0..7
  const int c0 = (lane & 3) * 2;     // 0,2,4,6

  const float* pxa = chars + ((size_t)bb * kT * kS + (ss + lr)) * (size_t)kC;
  const float* pxb = pxa + 8 * kC;
  const size_t tstride = (size_t)kS * kC;

  // ldsm4 lane offset for B fragments
  const int sel = lane >> 3;
  const int b_lane_off = ((lane & 7) + 8 * (sel >> 1)) * (PITCH * 2) + (sel & 1) * 16;
  const uint32_t wih_b = smem_u32(wih_s) + b_lane_off;
  const uint32_t whh_b = smem_u32(whh_s) + b_lane_off;

  // h state in f32 C-fragment layout; tile j covers cols 8j..8j+7
  float hf[8][4];
#pragma unroll
  for (int j = 0; j < 8; ++j)
#pragma unroll
    for (int e = 0; e < 4; ++e) hf[j][e] = 0.0f;

  for (int t = 0; t < kT; ++t) {
    // ---- load x_t and pack to fp16 A-fragments immediately ----
    uint32_t xa[4][4];  // [kk][frag]
#pragma unroll
    for (int kk = 0; kk < 4; ++kk) {
      const float2 v0 = *reinterpret_cast<const float2*>(pxa + 16 * kk + c0);
      const float2 v1 = *reinterpret_cast<const float2*>(pxb + 16 * kk + c0);
      const float2 v2 = *reinterpret_cast<const float2*>(pxa + 16 * kk + 8 + c0);
      const float2 v3 = *reinterpret_cast<const float2*>(pxb + 16 * kk + 8 + c0);
      xa[kk][0] = pack_f16x2(v0.x, v0.y);
      xa[kk][1] = pack_f16x2(v1.x, v1.y);
      xa[kk][2] = pack_f16x2(v2.x, v2.y);
      xa[kk][3] = pack_f16x2(v3.x, v3.y);
    }
    pxa += tstride;
    pxb += tstride;

    // pack h A-fragments (C-frag layout matches A-frag layout)
    uint32_t ha[4][4];
#pragma unroll
    for (int kk = 0; kk < 4; ++kk) {
      ha[kk][0] = pack_f16x2(hf[2 * kk][0], hf[2 * kk][1]);
      ha[kk][1] = pack_f16x2(hf[2 * kk][2], hf[2 * kk][3]);
      ha[kk][2] = pack_f16x2(hf[2 * kk + 1][0], hf[2 * kk + 1][1]);
      ha[kk][3] = pack_f16x2(hf[2 * kk + 1][2], hf[2 * kk + 1][3]);
    }

    // accumulators: tiles 0-7 r, 8-15 z, 16-23 n(x-path); accHN = h-n-path
    float acc[24][4];
    float accHN[8][4];
#pragma unroll
    for (int j = 0; j < 24; ++j)
#pragma unroll
      for (int e = 0; e < 4; ++e) acc[j][e] = 0.0f;
#pragma unroll
    for (int j = 0; j < 8; ++j)
#pragma unroll
      for (int e = 0; e < 4; ++e) accHN[j][e] = 0.0f;

    // ---- h-path GEMM: gh = h @ Whh^T (depth-1 rotating prefetch) ----
    {
      uint32_t bcur[4], bnext[4];
      ldsm4(bcur, whh_b);  // kk=0, jp=0
#pragma unroll
      for (int kk = 0; kk < 4; ++kk) {
#pragma unroll
        for (int jp = 0; jp < 12; ++jp) {
          const int nkk = (jp == 11) ? kk + 1 : kk;
          const int njp = (jp == 11) ? 0 : jp + 1;
          if (!(kk == 3 && jp == 11)) {
            ldsm4(bnext, whh_b + nkk * 32 + njp * (16 * PITCH * 2));
          }
          float* d0 = (jp < 8) ? acc[2 * jp] : accHN[2 * (jp - 8)];
          float* d1 = (jp < 8) ? acc[2 * jp + 1] : accHN[2 * (jp - 8) + 1];
          mma16816(d0, ha[kk], bcur[0], bcur[1]);
          mma16816(d1, ha[kk], bcur[2], bcur[3]);
          bcur[0] = bnext[0]; bcur[1] = bnext[1];
          bcur[2] = bnext[2]; bcur[3] = bnext[3];
        }
      }
    }

    // ---- x-path GEMM: gi = x @ Wih^T (depth-1 rotating prefetch) ----
    {
      uint32_t bcur[4], bnext[4];
      ldsm4(bcur, wih_b);
#pragma unroll
      for (int kk = 0; kk < 4; ++kk) {
#pragma unroll
        for (int jp = 0; jp < 12; ++jp) {
          const int nkk = (jp == 11) ? kk + 1 : kk;
          const int njp = (jp == 11) ? 0 : jp + 1;
          if (!(kk == 3 && jp == 11)) {
            ldsm4(bnext, wih_b + nkk * 32 + njp * (16 * PITCH * 2));
          }
          mma16816(acc[2 * jp], xa[kk], bcur[0], bcur[1]);
          mma16816(acc[2 * jp + 1], xa[kk], bcur[2], bcur[3]);
          bcur[0] = bnext[0]; bcur[1] = bnext[1];
          bcur[2] = bnext[2]; bcur[3] = bnext[3];
        }
      }
    }

    // ---- elementwise GRU update via MUFU.TANH (~11 instr / 3 MUFU per elem) ----
#pragma unroll
    for (int j = 0; j < 8; ++j) {
      const float2 bR = *reinterpret_cast<const float2*>(brz + 8 * j + c0);
      const float2 bZ = *reinterpret_cast<const float2*>(brz + 64 + 8 * j + c0);
      const float2 bN = *reinterpret_cast<const float2*>(bin_s + 8 * j + c0);
      const float2 bHN = *reinterpret_cast<const float2*>(bhn_s + 8 * j + c0);
#pragma unroll
      for (int e = 0; e < 4; ++e) {
        const float br = (e & 1) ? bR.y : bR.x;
        const float bz = (e & 1) ? bZ.y : bZ.x;
        const float bn = (e & 1) ? bN.y : bN.x;
        const float bhn = (e & 1) ? bHN.y : bHN.x;
        // sigmoid(g + b) with b pre-scaled: arg = 0.5*g + (0.5*b)
        const float r = fsigmoid_half(fmaf(0.5f, acc[j][e], br));
        const float z = fsigmoid_half(fmaf(0.5f, acc[8 + j][e], bz));
        const float n = ftanh(acc[16 + j][e] + bn + r * (accHN[j][e] + bhn));
        hf[j][e] = n + z * (hf[j][e] - n);
      }
    }
  }

  // ---- write final h (f32 state, exact) ----
  {
    float* poa = out + (size_t)(warp_row0 + lr) * kH;
    float* pob = out + (size_t)(warp_row0 + lr + 8) * kH;
#pragma unroll
    for (int j = 0; j < 8; ++j) {
      float2 va, vb;
      va.x = hf[j][0]; va.y = hf[j][1];
      vb.x = hf[j][2]; vb.y = hf[j][3];
      *reinterpret_cast<float2*>(poa + 8 * j + c0) = va;
      *reinterpret_cast<float2*>(pob + 8 * j + c0) = vb;
    }
  }
}

extern "C" void kernel_launch(void* const* d_in, const int* in_sizes, int n_in,
                              void* d_out, int out_size) {
  const float* chars = (const float*)d_in[0];
  const float* Wih = (const float*)d_in[1];
  const float* Whh = (const float*)d_in[2];
  const float* bih = (const float*)d_in[3];
  const float* bhh = (const float*)d_in[4];
  float* out = (float*)d_out;

  cudaFuncSetAttribute(gru_fused_kernel,
                       cudaFuncAttributeMaxDynamicSharedMemorySize, SMEM_BYTES);

  const int grid = NROWS / (16 * 8);  // 250 CTAs, 8 warps each, 16 rows/warp
  gru_fused_kernel<<<grid, THREADS, SMEM_BYTES>>>(chars, Wih, Whh, bih, bhh, out);
}